// round 9
// baseline (speedup 1.0000x reference)
#include <cuda_runtime.h>

// ---------------------------------------------------------------------------
// Single-sequence (batch row 255) 2-layer LSTM.
// R5 topology (separate layer-1 / layer-2 CTA groups, tagged u64 pairs,
// poll-IS-the-data-load) + per-warp unit ownership -> in-warp activation.
// Round 9: fixed R8's deadlock (bottom-of-loop staging prefetched tag
// total+1 which is never produced; staging now guarded on last iteration).
// ---------------------------------------------------------------------------

#define HT   512
#define NAC  64     // layer-1 CTAs, 8 units each
#define NBC  64     // layer-2 CTAs, 8 units each
#define NBLK 128
#define NTHR 256
#define R1   16     // h1 ring depth (A->B skew via backpressure)
#define R2   4      // h2 ring depth
#define RO   4      // o ring depth

typedef unsigned long long u64;

__device__ __align__(16) u64 g_h1p[R1][HT];
__device__ __align__(16) u64 g_h2p[R2][HT];
__device__ __align__(16) u64 g_op[RO][NBC];
__device__ int g_prog[NBC * 32];      // B progress flags, 128B padded

__device__ __forceinline__ float sigf(float v)   { return 1.0f / (1.0f + __expf(-v)); }
__device__ __forceinline__ float tanhff(float v) { return 2.0f / (1.0f + __expf(-2.0f * v)) - 1.0f; }

__device__ __forceinline__ u64 ldp(const u64* p) {
    u64 v; asm volatile("ld.relaxed.gpu.global.b64 %0, [%1];" : "=l"(v) : "l"(p) : "memory"); return v;
}
__device__ __forceinline__ void stp(u64* p, u64 v) {
    asm volatile("st.relaxed.gpu.global.b64 [%0], %1;" :: "l"(p), "l"(v) : "memory");
}
__device__ __forceinline__ int ldacq(const int* p) {
    int v; asm volatile("ld.acquire.gpu.global.b32 %0, [%1];" : "=r"(v) : "l"(p) : "memory"); return v;
}
__device__ __forceinline__ void strel(int* p, int v) {
    asm volatile("st.release.gpu.global.b32 [%0], %1;" :: "l"(p), "r"(v) : "memory");
}
__device__ __forceinline__ u64 mkpair(float f, unsigned tag) {
    return ((u64)tag << 32) | (u64)__float_as_uint(f);
}
__device__ __forceinline__ float pval(u64 v) { return __uint_as_float((unsigned)v); }
__device__ __forceinline__ unsigned ptag(u64 v) { return (unsigned)(v >> 32); }

__device__ __forceinline__ u64 fma2(u64 a, u64 b, u64 c) {
    u64 d;
    asm("fma.rn.f32x2 %0, %1, %2, %3;" : "=l"(d) : "l"(a), "l"(b), "l"(c));
    return d;
}
__device__ __forceinline__ float hsum2(u64 a) {
    return __uint_as_float((unsigned)a) + __uint_as_float((unsigned)(a >> 32));
}

__global__ void init_state_kernel() {
    int tid = threadIdx.x;
    for (int i = tid; i < R1 * HT;  i += NTHR) ((u64*)g_h1p)[i] = 0ull;  // tag 0, val 0
    for (int i = tid; i < R2 * HT;  i += NTHR) ((u64*)g_h2p)[i] = 0ull;
    for (int i = tid; i < RO * NBC; i += NTHR) ((u64*)g_op)[i]  = 0ull;
    for (int i = tid; i < NBC * 32; i += NTHR) g_prog[i] = 0;
}

__global__ void __launch_bounds__(NTHR, 1) lstm_warpunit_kernel(
    const float* __restrict__ input,
    const float* __restrict__ Wih1, const float* __restrict__ Whh1,
    const float* __restrict__ bih1, const float* __restrict__ bhh1,
    const float* __restrict__ Wih2, const float* __restrict__ Whh2,
    const float* __restrict__ bih2, const float* __restrict__ bhh2,
    const float* __restrict__ Wlin, const float* __restrict__ blin,
    float* __restrict__ out, int T, int pred_len, int Brows)
{
    __shared__ __align__(16) float sh_a[2][HT];   // h1 double buffer
    __shared__ __align__(16) float sh_b[2][HT];   // h2 double buffer (B only)
    __shared__ float sxin[1024];
    __shared__ u64 sxs;                            // tagged decode x broadcast
    __shared__ u64 swo[8];                         // tagged per-warp o partials (B)

    const int tid  = threadIdx.x;
    const int wid  = tid >> 5;      // 8 warps; warp w owns unit w
    const int lane = tid & 31;
    const int total = T + pred_len - 1;

    if (blockIdx.x < NAC) {
        // ===================== GROUP A : layer 1 =====================
        const int bA = blockIdx.x * 8;
        // warp w: gates 0..3 of unit bA+w, K=512
        u64 wA[4][8];
        float bb[4], wx[4];
        #pragma unroll
        for (int g = 0; g < 4; ++g) {
            int R = (g << 9) + bA + wid;
            const u64* Wr = (const u64*)(Whh1 + (size_t)R * HT);
            #pragma unroll
            for (int p = 0; p < 8; ++p) wA[g][p] = Wr[lane + 32 * p];
            bb[g] = bih1[R] + bhh1[R];
            wx[g] = Wih1[R];
        }
        const float* xin = input + (size_t)(Brows - 1) * T;
        for (int i = tid; i < T && i < 1024; i += NTHR) sxin[i] = xin[i];
        if (tid == 0) sxs = 0ull;
        const float blin0 = blin[0];
        float c1 = 0.f;   // uniform across lanes of each warp

        // prologue: stage h1 tag 0 into buf 0
        {
            const u64* p0 = &g_h1p[0][tid];
            const u64* p1 = p0 + 256;
            u64 v0, v1; bool o0 = false, o1 = false;
            do {
                if (!o0) { v0 = ldp(p0); o0 = (ptag(v0) == 0u); }
                if (!o1) { v1 = ldp(p1); o1 = (ptag(v1) == 0u); }
            } while (!(o0 && o1));
            sh_a[0][tid] = pval(v0);
            sh_a[0][tid + 256] = pval(v1);
        }
        __syncthreads();

        for (int t = 0; t < total; ++t) {
            const int buf = t & 1;

            // ---- matvec: 4 gate rows of unit wid, K=512 ----
            float s[4];
            {
                u64 hv[8];
                const u64* sp = (const u64*)sh_a[buf];
                #pragma unroll
                for (int p = 0; p < 8; ++p) hv[p] = sp[lane + 32 * p];
                #pragma unroll
                for (int g = 0; g < 4; ++g) {
                    u64 acc = 0ull;
                    #pragma unroll
                    for (int p = 0; p < 8; ++p) acc = fma2(wA[g][p], hv[p], acc);
                    float a = hsum2(acc);
                    #pragma unroll
                    for (int o = 16; o; o >>= 1) a += __shfl_xor_sync(0xffffffffu, a, o);
                    s[g] = a;   // all lanes
                }
            }

            // ---- x: encode from smem; decode via tagged broadcast ----
            float x;
            if (t < T) {
                x = sxin[t];
            } else if (wid == 0) {
                const u64* q0 = &g_op[t & (RO - 1)][lane];
                const u64* q1 = q0 + 32;
                u64 a0, a1; bool d0 = false, d1 = false;
                do {
                    if (!d0) { a0 = ldp(q0); d0 = (ptag(a0) == (unsigned)t); }
                    if (!d1) { a1 = ldp(q1); d1 = (ptag(a1) == (unsigned)t); }
                } while (!(d0 && d1));
                float ov = pval(a0) + pval(a1);
                #pragma unroll
                for (int o = 16; o; o >>= 1) ov += __shfl_xor_sync(0xffffffffu, ov, o);
                x = ov + blin0;
                if (lane == 0) {
                    *(volatile u64*)&sxs = mkpair(x, (unsigned)t);
                    if (blockIdx.x == 0) out[t - T] = x;
                }
            } else {
                u64 vv;
                do { vv = *(volatile u64*)&sxs; } while (ptag(vv) != (unsigned)t);
                x = pval(vv);
            }

            // ---- backpressure on h1 ring (amortized, per warp) ----
            if ((t & 7) == 0 && t >= 16) {
                int need = t - 8;
                const int* pp0 = &g_prog[lane * 32];
                const int* pp1 = &g_prog[(lane + 32) * 32];
                for (;;) {
                    bool ok = (ldacq(pp0) >= need) && (ldacq(pp1) >= need);
                    if (__ballot_sync(0xffffffffu, ok) == 0xffffffffu) break;
                }
            }

            // ---- in-warp activation + publish h1(t) tag t+1 ----
            {
                float vi = s[0] + bb[0] + x * wx[0];
                float vf = s[1] + bb[1] + x * wx[1];
                float vg = s[2] + bb[2] + x * wx[2];
                float vo = s[3] + bb[3] + x * wx[3];
                float i_ = sigf(vi), f_ = sigf(vf), g_ = tanhff(vg), o_ = sigf(vo);
                c1 = f_ * c1 + i_ * g_;
                float hh = o_ * tanhff(c1);
                if (lane == 0)
                    stp(&g_h1p[(t + 1) & (R1 - 1)][bA + wid], mkpair(hh, (unsigned)(t + 1)));
            }

            // ---- stage h1 tag t+1 into buf (t+1)&1 (skip on last iter) ----
            if (t + 1 < total) {
                const int tg = t + 1;
                const u64* p0 = &g_h1p[tg & (R1 - 1)][tid];
                const u64* p1 = p0 + 256;
                u64 v0, v1; bool o0 = false, o1 = false;
                do {
                    if (!o0) { v0 = ldp(p0); o0 = (ptag(v0) == (unsigned)tg); }
                    if (!o1) { v1 = ldp(p1); o1 = (ptag(v1) == (unsigned)tg); }
                } while (!(o0 && o1));
                sh_a[tg & 1][tid] = pval(v0);
                sh_a[tg & 1][tid + 256] = pval(v1);
                __syncthreads();
            }
        }

        // ---- epilogue: o tag total -> out[pred_len-1] ----
        if (blockIdx.x == 0 && wid == 0) {
            const u64* q0 = &g_op[total & (RO - 1)][lane];
            const u64* q1 = q0 + 32;
            u64 a0, a1; bool d0 = false, d1 = false;
            do {
                if (!d0) { a0 = ldp(q0); d0 = (ptag(a0) == (unsigned)total); }
                if (!d1) { a1 = ldp(q1); d1 = (ptag(a1) == (unsigned)total); }
            } while (!(d0 && d1));
            float ov = pval(a0) + pval(a1);
            #pragma unroll
            for (int o = 16; o; o >>= 1) ov += __shfl_xor_sync(0xffffffffu, ov, o);
            if (lane == 0) out[pred_len - 1] = ov + blin0;
        }
    } else {
        // ===================== GROUP B : layer 2 =====================
        const int jB = blockIdx.x - NAC;
        const int bB = jB * 8;
        // warp w: gates 0..3 of unit bB+w, K=1024 [h1 | h2]
        u64 wB[4][16];
        float bb[4];
        #pragma unroll
        for (int g = 0; g < 4; ++g) {
            int R = (g << 9) + bB + wid;
            const u64* Wi = (const u64*)(Wih2 + (size_t)R * HT);
            const u64* Wh = (const u64*)(Whh2 + (size_t)R * HT);
            #pragma unroll
            for (int p = 0; p < 8; ++p) {
                wB[g][p]     = Wi[lane + 32 * p];
                wB[g][8 + p] = Wh[lane + 32 * p];
            }
            bb[g] = bih2[R] + bhh2[R];
        }
        const float wlin_w = Wlin[bB + wid];
        if (tid < 8) swo[tid] = 0ull;
        float c2 = 0.f;

        // prologue: stage h1 tag 1 & h2 tag 0 into buf 0
        {
            const u64* p0 = &g_h1p[1 & (R1 - 1)][tid];
            const u64* p1 = p0 + 256;
            const u64* q0 = &g_h2p[0][tid];
            const u64* q1 = q0 + 256;
            u64 v0, v1, w0, w1;
            bool o0 = false, o1 = false, o2 = false, o3 = false;
            do {
                if (!o0) { v0 = ldp(p0); o0 = (ptag(v0) == 1u); }
                if (!o1) { v1 = ldp(p1); o1 = (ptag(v1) == 1u); }
                if (!o2) { w0 = ldp(q0); o2 = (ptag(w0) == 0u); }
                if (!o3) { w1 = ldp(q1); o3 = (ptag(w1) == 0u); }
            } while (!(o0 && o1 && o2 && o3));
            sh_a[0][tid] = pval(v0);  sh_a[0][tid + 256] = pval(v1);
            sh_b[0][tid] = pval(w0);  sh_b[0][tid + 256] = pval(w1);
        }
        __syncthreads();

        for (int k = 0; k < total; ++k) {
            const int buf = k & 1;
            if (tid == 0) strel(&g_prog[jB * 32], k);   // consumed h1 slot tag k+1

            // ---- matvec: 4 gate rows of unit wid, K=1024 ----
            float s[4];
            {
                u64 hv[16];
                const u64* s1 = (const u64*)sh_a[buf];
                const u64* s2 = (const u64*)sh_b[buf];
                #pragma unroll
                for (int p = 0; p < 8; ++p) {
                    hv[p]     = s1[lane + 32 * p];
                    hv[8 + p] = s2[lane + 32 * p];
                }
                #pragma unroll
                for (int g = 0; g < 4; ++g) {
                    u64 acc = 0ull;
                    #pragma unroll
                    for (int p = 0; p < 16; ++p) acc = fma2(wB[g][p], hv[p], acc);
                    float a = hsum2(acc);
                    #pragma unroll
                    for (int o = 16; o; o >>= 1) a += __shfl_xor_sync(0xffffffffu, a, o);
                    s[g] = a;
                }
            }

            // ---- in-warp activation + publish h2 tag k+1 ----
            float hh;
            {
                float i_ = sigf(s[0] + bb[0]);
                float f_ = sigf(s[1] + bb[1]);
                float g_ = tanhff(s[2] + bb[2]);
                float o_ = sigf(s[3] + bb[3]);
                c2 = f_ * c2 + i_ * g_;
                hh = o_ * tanhff(c2);
                if (lane == 0)
                    stp(&g_h2p[(k + 1) & (R2 - 1)][bB + wid], mkpair(hh, (unsigned)(k + 1)));
            }

            // ---- o partial: tagged smem gather, warp0 publishes ----
            if (k >= T - 1) {
                if (lane == 0)
                    *(volatile u64*)&swo[wid] = mkpair(wlin_w * hh, (unsigned)(k + 1));
                if (wid == 0) {
                    u64 vv = 0ull;
                    for (;;) {
                        bool d = true;
                        if (lane < 8) {
                            vv = *(volatile u64*)&swo[lane];
                            d = (ptag(vv) == (unsigned)(k + 1));
                        }
                        if (__ballot_sync(0xffffffffu, d) == 0xffffffffu) break;
                    }
                    float p = (lane < 8) ? pval(vv) : 0.f;
                    p += __shfl_xor_sync(0xffffffffu, p, 4);
                    p += __shfl_xor_sync(0xffffffffu, p, 2);
                    p += __shfl_xor_sync(0xffffffffu, p, 1);
                    if (lane == 0)
                        stp(&g_op[(k + 1) & (RO - 1)][jB], mkpair(p, (unsigned)(k + 1)));
                }
            }

            // ---- stage h1 tag k+2, h2 tag k+1 into buf (k+1)&1 (skip on last iter) ----
            if (k + 1 < total) {
                const int t1 = k + 2, t2 = k + 1, nb = (k + 1) & 1;
                const u64* p0 = &g_h1p[t1 & (R1 - 1)][tid];
                const u64* p1 = p0 + 256;
                const u64* q0 = &g_h2p[t2 & (R2 - 1)][tid];
                const u64* q1 = q0 + 256;
                u64 v0, v1, w0, w1;
                bool o0 = false, o1 = false, o2 = false, o3 = false;
                do {
                    if (!o2) { w0 = ldp(q0); o2 = (ptag(w0) == (unsigned)t2); }
                    if (!o3) { w1 = ldp(q1); o3 = (ptag(w1) == (unsigned)t2); }
                    if (!o0) { v0 = ldp(p0); o0 = (ptag(v0) == (unsigned)t1); }
                    if (!o1) { v1 = ldp(p1); o1 = (ptag(v1) == (unsigned)t1); }
                } while (!(o0 && o1 && o2 && o3));
                sh_a[nb][tid] = pval(v0);  sh_a[nb][tid + 256] = pval(v1);
                sh_b[nb][tid] = pval(w0);  sh_b[nb][tid + 256] = pval(w1);
                __syncthreads();
            }
        }
    }
}

extern "C" void kernel_launch(void* const* d_in, const int* in_sizes, int n_in,
                              void* d_out, int out_size) {
    int off = (n_in >= 12 && in_sizes[1] == 1) ? 2 : 1;

    const float* input = (const float*)d_in[0];
    const float* Wih1  = (const float*)d_in[off + 0];
    const float* Whh1  = (const float*)d_in[off + 1];
    const float* bih1  = (const float*)d_in[off + 2];
    const float* bhh1  = (const float*)d_in[off + 3];
    const float* Wih2  = (const float*)d_in[off + 4];
    const float* Whh2  = (const float*)d_in[off + 5];
    const float* bih2  = (const float*)d_in[off + 6];
    const float* bhh2  = (const float*)d_in[off + 7];
    const float* Wlin  = (const float*)d_in[off + 8];
    const float* blin  = (const float*)d_in[off + 9];

    const int B = 256;
    const int T = in_sizes[0] / B;
    const int pred_len = out_size;

    init_state_kernel<<<1, NTHR>>>();
    lstm_warpunit_kernel<<<NBLK, NTHR>>>(
        input, Wih1, Whh1, bih1, bhh1, Wih2, Whh2, bih2, bhh2, Wlin, blin,
        (float*)d_out, T, pred_len, B);
}